// round 14
// baseline (speedup 1.0000x reference)
#include <cuda_runtime.h>
#include <cstdint>
#include <math.h>

// ---------------- problem constants ----------------
#define BB 2
#define HH 240
#define WW 1216
#define CHN 27
#define OC 81
#define HWSZ (HH*WW)
#define NPIX (BB*HWSZ)

#define GX 38            // 1216/32
#define GY 60            // 240/4
#define UCOL 128         // column stride in U (per k,c row)

// ---------------- device scratch ----------------
__device__ float g_conv[(size_t)OC * NPIX];              // conv output planes [oc][b][y][x]
__device__ __align__(16) float g_U[16 * 27 * UCOL];      // Winograd weights, warp-permuted (L2-resident)

// ---------------- smem layout (bytes) ----------------
#define PSTR 36                            // patch row stride (floats), 34 used
#define SM_BIAS 0                          // 96 floats -> 384
#define SM_PATCH 384                       // 27*6*36*4 = 23328
#define SM_V (384 + 23328)                 // 23712; 16*27*32*4 = 55296
#define SM_TOTAL (SM_V + 55296)            // 79008  (2 CTAs/SM: 158016 <= 228KB)

// ---------------- prep: U = G g G^T, warp-permuted [k][c][128] ----------------
// oc = w + 8*j  ->  column 16*w + j  (w = 0..7, j = 0..11; j=12..15 pad zero)
__global__ void prep_kernel(const float* __restrict__ conv_w) {
    int idx = blockIdx.x * 256 + threadIdx.x;
    if (idx >= 27 * UCOL) return;
    int c = idx / UCOL;
    int col = idx % UCOL;
    int w = col >> 4, j = col & 15;
    int oc = w + 8 * j;
    bool valid = (j < 12) && (oc < OC);

    float U[4][4];
    if (valid) {
        float g[3][3];
        #pragma unroll
        for (int ky = 0; ky < 3; ky++)
            #pragma unroll
            for (int kx = 0; kx < 3; kx++)
                g[ky][kx] = conv_w[((oc * CHN + c) * 3 + ky) * 3 + kx];
        float T[4][3];
        #pragma unroll
        for (int kx = 0; kx < 3; kx++) {
            T[0][kx] = g[0][kx];
            T[1][kx] = 0.5f * (g[0][kx] + g[1][kx] + g[2][kx]);
            T[2][kx] = 0.5f * (g[0][kx] - g[1][kx] + g[2][kx]);
            T[3][kx] = g[2][kx];
        }
        #pragma unroll
        for (int r = 0; r < 4; r++) {
            U[r][0] = T[r][0];
            U[r][1] = 0.5f * (T[r][0] + T[r][1] + T[r][2]);
            U[r][2] = 0.5f * (T[r][0] - T[r][1] + T[r][2]);
            U[r][3] = T[r][2];
        }
    } else {
        #pragma unroll
        for (int r = 0; r < 4; r++)
            #pragma unroll
            for (int s = 0; s < 4; s++) U[r][s] = 0.f;
    }
    #pragma unroll
    for (int r = 0; r < 4; r++)
        #pragma unroll
        for (int s = 0; s < 4; s++)
            g_U[((r * 4 + s) * 27 + c) * UCOL + col] = U[r][s];
}

// ---------------- Winograd conv kernel: 256 threads, 8 warps x 12 oc, 2 CTAs/SM ----------------
__global__ __launch_bounds__(256, 2)
void wino_kernel(const float* __restrict__ guide, const float* __restrict__ conv_b) {
    extern __shared__ uint8_t smem[];
    const int tid = threadIdx.x;
    const int wid = tid >> 5;          // 0..7
    const int lane = tid & 31;
    const int bx = blockIdx.x, by = blockIdx.y, bz = blockIdx.z;

    if (tid < 96) ((float*)(smem + SM_BIAS))[tid] = (tid < OC) ? conv_b[tid] : 0.f;

    // --- stage input patch: 27 ch x 6 rows x 34 cols (zero-padded), stride 36 ---
    {
        const int py0 = 4 * by - 1;
        const int px0 = 32 * bx - 1;
        float* patch = (float*)(smem + SM_PATCH);
        for (int i = tid; i < 27 * 6 * 34; i += 256) {
            int c = i / 204;
            int rr = (i / 34) % 6;
            int xx = i % 34;
            int gy = py0 + rr;
            int gx = px0 + xx;
            float v = 0.f;
            if ((unsigned)gy < HH && (unsigned)gx < WW)
                v = __ldg(&guide[((size_t)(bz * CHN + c) * HH + gy) * WW + gx]);
            patch[(c * 6 + rr) * PSTR + xx] = v;
        }
    }
    __syncthreads();

    // --- input transform V = B^T d B; tile index t = tx + 16*tyl (tx 0..15, tyl 0..1) ---
    {
        const float* patch = (const float*)(smem + SM_PATCH);
        float* V = (float*)(smem + SM_V);
        for (int i = tid; i < 27 * 32; i += 256) {
            int c = i >> 5;
            int t = i & 31;
            int tx = t & 15;
            int tyl = t >> 4;
            const float* base = patch + (c * 6 + tyl * 2) * PSTR + 2 * tx;
            float d[4][4];
            #pragma unroll
            for (int r = 0; r < 4; r++) {
                float2 p0 = *(const float2*)(base + r * PSTR);
                float2 p1 = *(const float2*)(base + r * PSTR + 2);
                d[r][0] = p0.x; d[r][1] = p0.y; d[r][2] = p1.x; d[r][3] = p1.y;
            }
            float R[4][4];
            #pragma unroll
            for (int r = 0; r < 4; r++) {
                R[r][0] = d[r][0] - d[r][2];
                R[r][1] = d[r][1] + d[r][2];
                R[r][2] = d[r][2] - d[r][1];
                R[r][3] = d[r][1] - d[r][3];
            }
            #pragma unroll
            for (int s = 0; s < 4; s++) {
                V[((0 * 4 + s) * 27 + c) * 32 + t] = R[0][s] - R[2][s];
                V[((1 * 4 + s) * 27 + c) * 32 + t] = R[1][s] + R[2][s];
                V[((2 * 4 + s) * 27 + c) * 32 + t] = R[2][s] - R[1][s];
                V[((3 * 4 + s) * 27 + c) * 32 + t] = R[1][s] - R[3][s];
            }
        }
    }
    __syncthreads();   // the ONLY barrier before the epilogue: V is read-only from here

    // --- 16 position-GEMMs, U streamed from L2 via uniform LDG, fused output transform ---
    float Y[4][12];
    #pragma unroll
    for (int q = 0; q < 4; q++)
        #pragma unroll
        for (int j = 0; j < 12; j++) Y[q][j] = 0.f;

    #pragma unroll 1
    for (int k = 0; k < 16; k++) {
        const float* Uk = g_U + (size_t)(k * 27) * UCOL + wid * 16;
        const float* Vk = (const float*)(smem + SM_V) + k * 27 * 32 + lane;

        float m[12];
        #pragma unroll
        for (int j = 0; j < 12; j++) m[j] = 0.f;
        #pragma unroll 3
        for (int c = 0; c < 27; c++) {
            float v = Vk[c * 32];
            float4 u0 = __ldg((const float4*)(Uk + c * UCOL));
            float4 u1 = __ldg((const float4*)(Uk + c * UCOL + 4));
            float4 u2 = __ldg((const float4*)(Uk + c * UCOL + 8));
            m[0]  = fmaf(u0.x, v, m[0]);  m[1]  = fmaf(u0.y, v, m[1]);
            m[2]  = fmaf(u0.z, v, m[2]);  m[3]  = fmaf(u0.w, v, m[3]);
            m[4]  = fmaf(u1.x, v, m[4]);  m[5]  = fmaf(u1.y, v, m[5]);
            m[6]  = fmaf(u1.z, v, m[6]);  m[7]  = fmaf(u1.w, v, m[7]);
            m[8]  = fmaf(u2.x, v, m[8]);  m[9]  = fmaf(u2.y, v, m[9]);
            m[10] = fmaf(u2.z, v, m[10]); m[11] = fmaf(u2.w, v, m[11]);
        }

        // output-transform accumulation: coef(p,q) = A_p[r]*A_q[s]
        int r = k >> 2, s = k & 3;
        float A0r = (r == 3) ? 0.f : 1.f;
        float A1r = (r == 0) ? 0.f : ((r == 1) ? 1.f : -1.f);
        float A0s = (s == 3) ? 0.f : 1.f;
        float A1s = (s == 0) ? 0.f : ((s == 1) ? 1.f : -1.f);
        float cc[4] = { A0r * A0s, A0r * A1s, A1r * A0s, A1r * A1s };
        #pragma unroll
        for (int q = 0; q < 4; q++) {
            if (cc[q] != 0.f) {
                #pragma unroll
                for (int j = 0; j < 12; j++)
                    Y[q][j] = fmaf(cc[q], m[j], Y[q][j]);
            }
        }
    }

    // --- epilogue: bias + 2x STG.64 per oc ---
    {
        const float* bias = (const float*)(smem + SM_BIAS);
        const int xcol = 32 * bx + 2 * (lane & 15);
        const int row0 = 4 * by + 2 * (lane >> 4);
        const size_t base = (size_t)bz * HWSZ + xcol;
        #pragma unroll
        for (int j = 0; j < 12; j++) {
            int oc = wid + 8 * j;
            if (oc >= OC) break;
            float bv = bias[oc];
            float* plane = g_conv + (size_t)oc * NPIX + base;
            *(float2*)(plane + (size_t)row0 * WW)       = make_float2(Y[0][j] + bv, Y[1][j] + bv);
            *(float2*)(plane + (size_t)(row0 + 1) * WW) = make_float2(Y[2][j] + bv, Y[3][j] + bv);
        }
    }
}

// ---------------- propagation: softmax + bilinear-zeros + confidence blend ----------------
__device__ __constant__ float TAPX[9] = {-1.f, 0.f, 1.f, -1.f, 0.f, 1.f, -1.f, 0.f, 1.f};
__device__ __constant__ float TAPY[9] = {-1.f, -1.f, -1.f, 0.f, 0.f, 0.f, 1.f, 1.f, 1.f};

__global__ void prop_kernel(const float* __restrict__ prev,
                            const float* __restrict__ sp_dep,
                            const float* __restrict__ confid,
                            float* __restrict__ out_cur,
                            float* __restrict__ pred_out,
                            const float* __restrict__ feat_src,
                            float* __restrict__ feat_dst,
                            int iter) {
    int p = blockIdx.x * blockDim.x + threadIdx.x;
    if (p >= NPIX) return;
    int b = p / HWSZ;
    int rem = p % HWSZ;
    int y = rem / WW;
    int x = rem % WW;
    const float* img = prev + (size_t)b * HWSZ;

    // ---- front-load all independent global reads (max MLP) ----
    float araw[9], ox[9], oy[9];
    #pragma unroll
    for (int t = 0; t < 9; t++)
        araw[t] = __ldg(&g_conv[(size_t)(54 + iter * 9 + t) * NPIX + p]);
    #pragma unroll
    for (int t = 0; t < 9; t++) {
        ox[t] = __ldg(&g_conv[(size_t)((iter * 9 + t) * 2) * NPIX + p]);
        oy[t] = __ldg(&g_conv[(size_t)((iter * 9 + t) * 2 + 1) * NPIX + p]);
    }
    float sp = __ldg(&sp_dep[p]);
    float cfr = __ldg(&confid[p]);

    // softmax weights
    float mx = araw[0];
    #pragma unroll
    for (int t = 1; t < 9; t++) mx = fmaxf(mx, araw[t]);
    float wv[9];
    float s = 0.f;
    #pragma unroll
    for (int t = 0; t < 9; t++) { wv[t] = __expf(araw[t] - mx); s += wv[t]; }
    float inv = 1.f / s;

    float agg = 0.f;
    #pragma unroll
    for (int t = 0; t < 9; t++) {
        float px = ox[t] + TAPX[t] + (float)x;
        float py = oy[t] + TAPY[t] + (float)y;
        float x0f = floorf(px), y0f = floorf(py);
        int xi = (int)x0f, yi = (int)y0f;
        float wx = px - x0f, wy = py - y0f;

        float v00 = 0.f, v01 = 0.f, v10 = 0.f, v11 = 0.f;
        bool xa = (xi >= 0) & (xi < WW);
        bool xb2 = (xi + 1 >= 0) & (xi + 1 < WW);
        bool ya = (yi >= 0) & (yi < HH);
        bool yb = (yi + 1 >= 0) & (yi + 1 < HH);
        if (ya) {
            const float* r0 = img + (size_t)yi * WW;
            if (xa) v00 = __ldg(r0 + xi);
            if (xb2) v01 = __ldg(r0 + xi + 1);
        }
        if (yb) {
            const float* r1 = img + (size_t)(yi + 1) * WW;
            if (xa) v10 = __ldg(r1 + xi);
            if (xb2) v11 = __ldg(r1 + xi + 1);
        }
        float v = (1.f - wy) * ((1.f - wx) * v00 + wx * v01)
                + wy * ((1.f - wx) * v10 + wx * v11);
        agg += wv[t] * v;
    }
    agg *= inv;

    float cf = 1.f / (1.f + __expf(-cfr));
    float sg = (sp > 0.f) ? 1.f : ((sp < 0.f) ? -1.f : 0.f);
    cf *= sg;
    float o = (1.f - cf) * agg + cf * sp;

    out_cur[p] = o;
    if (pred_out) pred_out[p] = o;
    if (feat_dst) feat_dst[p] = feat_src[p];
}

// ---------------- launch ----------------
extern "C" void kernel_launch(void* const* d_in, const int* in_sizes, int n_in,
                              void* d_out, int out_size) {
    const float* input  = (const float*)d_in[0];
    const float* guide  = (const float*)d_in[1];
    const float* sp_dep = (const float*)d_in[2];
    const float* confid = (const float*)d_in[3];
    const float* conv_w = (const float*)d_in[4];
    const float* conv_b = (const float*)d_in[5];

    float* out = (float*)d_out;
    float* pred = out;
    float* feat = out + NPIX;
    float* inter = out + 2 * (size_t)NPIX;

    static bool attr_set = false;
    if (!attr_set) {
        cudaFuncSetAttribute(wino_kernel, cudaFuncAttributeMaxDynamicSharedMemorySize, SM_TOTAL);
        attr_set = true;
    }

    prep_kernel<<<(27 * UCOL + 255) / 256, 256>>>(conv_w);

    dim3 wgrid(GX, GY, BB);
    wino_kernel<<<wgrid, 256, SM_TOTAL>>>(guide, conv_b);

    int pb = (NPIX + 255) / 256;
    prop_kernel<<<pb, 256>>>(input, sp_dep, confid, inter, nullptr, input, feat, 0);
    prop_kernel<<<pb, 256>>>(inter, sp_dep, confid, inter + NPIX, nullptr, nullptr, nullptr, 1);
    prop_kernel<<<pb, 256>>>(inter + NPIX, sp_dep, confid, inter + 2 * (size_t)NPIX, pred, nullptr, nullptr, 2);
}

// round 15
// speedup vs baseline: 1.5405x; 1.5405x over previous
#include <cuda_runtime.h>
#include <cstdint>
#include <math.h>

// ---------------- problem constants ----------------
#define BB 2
#define HH 240
#define WW 1216
#define CHN 27
#define OC 81
#define HWSZ (HH*WW)
#define NPIX (BB*HWSZ)

#define GX 19            // 1216/64
#define GY 60            // 240/4
#define UCOL 128         // padded column stride in U (per k,c row)
#define UKB (27*UCOL*4)  // 13824 bytes per U_k buffer

// ---------------- device scratch ----------------
__device__ float g_conv[(size_t)OC * NPIX];              // conv output planes [oc][b][y][x]
__device__ __align__(16) float g_U[16 * 27 * UCOL];      // Winograd weights, warp-permuted (oc 0..79)
__device__ float g_U80[16 * 27];                         // Winograd weights for oc=80, [k][c]

// ---------------- smem layout (bytes) ----------------
#define SM_BIAS 0                          // 96 floats -> 384
#define SM_PATCH 384                       // 27*6*68*4 = 44064
#define SM_V (384 + 44064)                 // 44448; 16*27*64*4 = 110592
#define SM_U (SM_V + 110592)               // 155040 (16B aligned); 2*13824 = 27648
#define SM_M80 (SM_U + 2*UKB)              // 182688; 16*64*4 = 4096
#define SM_TOTAL (SM_M80 + 4096)           // 186784

// ---------------- helpers ----------------
#define CP16(dst, src) asm volatile("cp.async.ca.shared.global [%0], [%1], 16;" :: "r"(dst), "l"(src))
#define CP_COMMIT() asm volatile("cp.async.commit_group;")
#define CP_WAIT1() asm volatile("cp.async.wait_group 1;")
#define CP_WAIT0() asm volatile("cp.async.wait_group 0;")

__device__ __forceinline__ uint32_t smem_u32(const void* p) {
    uint32_t a;
    asm("{ .reg .u64 t; cvta.to.shared.u64 t, %1; cvt.u32.u64 %0, t; }" : "=r"(a) : "l"(p));
    return a;
}

__device__ __forceinline__ void wino_filter(const float* __restrict__ conv_w,
                                            int oc, int c, float U[4][4]) {
    float g[3][3];
    #pragma unroll
    for (int ky = 0; ky < 3; ky++)
        #pragma unroll
        for (int kx = 0; kx < 3; kx++)
            g[ky][kx] = conv_w[((oc * CHN + c) * 3 + ky) * 3 + kx];
    float T[4][3];
    #pragma unroll
    for (int kx = 0; kx < 3; kx++) {
        T[0][kx] = g[0][kx];
        T[1][kx] = 0.5f * (g[0][kx] + g[1][kx] + g[2][kx]);
        T[2][kx] = 0.5f * (g[0][kx] - g[1][kx] + g[2][kx]);
        T[3][kx] = g[2][kx];
    }
    #pragma unroll
    for (int r = 0; r < 4; r++) {
        U[r][0] = T[r][0];
        U[r][1] = 0.5f * (T[r][0] + T[r][1] + T[r][2]);
        U[r][2] = 0.5f * (T[r][0] - T[r][1] + T[r][2]);
        U[r][3] = T[r][2];
    }
}

// ---------------- prep: U = G g G^T ----------------
// main table: warp w covers ocs 5w..5w+4 at cols 8w..8w+4 (cols 8w+5..8w+7 zero)
// oc=80 goes to g_U80[k][c]
__global__ void prep_kernel(const float* __restrict__ conv_w) {
    int idx = blockIdx.x * 256 + threadIdx.x;
    if (idx < 27 * UCOL) {
        int c = idx / UCOL;
        int col = idx % UCOL;
        int w = col >> 3, j = col & 7;
        float U[4][4];
        if (j < 5) {
            wino_filter(conv_w, 5 * w + j, c, U);
        } else {
            #pragma unroll
            for (int r = 0; r < 4; r++)
                #pragma unroll
                for (int s = 0; s < 4; s++) U[r][s] = 0.f;
        }
        #pragma unroll
        for (int r = 0; r < 4; r++)
            #pragma unroll
            for (int s = 0; s < 4; s++)
                g_U[((r * 4 + s) * 27 + c) * UCOL + col] = U[r][s];
    } else if (idx < 27 * UCOL + 27) {
        int c = idx - 27 * UCOL;
        float U[4][4];
        wino_filter(conv_w, 80, c, U);
        #pragma unroll
        for (int r = 0; r < 4; r++)
            #pragma unroll
            for (int s = 0; s < 4; s++)
                g_U80[(r * 4 + s) * 27 + c] = U[r][s];
    }
}

// ---------------- Winograd conv kernel: 512 threads, 16 warps x 5 oc + oc80 pass ----------------
__global__ __launch_bounds__(512, 1)
void wino_kernel(const float* __restrict__ guide, const float* __restrict__ conv_b) {
    extern __shared__ uint8_t smem[];
    const uint32_t sbase = smem_u32(smem);
    const int tid = threadIdx.x;
    const int wid = tid >> 5;
    const int lane = tid & 31;
    const int bx = blockIdx.x, by = blockIdx.y, bz = blockIdx.z;

    // --- prefetch U_0 ---
    {
        const char* src = (const char*)g_U;
        uint32_t dst = sbase + SM_U;
        for (int j = tid; j < UKB / 16; j += 512)
            CP16(dst + j * 16, src + (size_t)j * 16);
        CP_COMMIT();
    }

    if (tid < 96) ((float*)(smem + SM_BIAS))[tid] = (tid < OC) ? conv_b[tid] : 0.f;

    // --- stage input patch: 27 ch x 6 rows x 66 cols (zero-padded), stride 68 ---
    {
        const int py0 = 4 * by - 1;
        const int px0 = 64 * bx - 1;
        float* patch = (float*)(smem + SM_PATCH);
        for (int i = tid; i < 27 * 6 * 66; i += 512) {
            int c = i / 396;
            int rr = (i / 66) % 6;
            int xx = i % 66;
            int gy = py0 + rr;
            int gx = px0 + xx;
            float v = 0.f;
            if ((unsigned)gy < HH && (unsigned)gx < WW)
                v = __ldg(&guide[((size_t)(bz * CHN + c) * HH + gy) * WW + gx]);
            patch[(c * 6 + rr) * 68 + xx] = v;
        }
    }
    __syncthreads();

    // --- input transform V = B^T d B; pair index t = tx + 32*tyl ---
    {
        const float* patch = (const float*)(smem + SM_PATCH);
        float* V = (float*)(smem + SM_V);
        for (int i = tid; i < 27 * 64; i += 512) {
            int c = i >> 6;
            int t = i & 63;
            int tx = t & 31;
            int tyl = t >> 5;
            const float* base = patch + (c * 6 + tyl * 2) * 68 + 2 * tx;
            float d[4][4];
            #pragma unroll
            for (int r = 0; r < 4; r++) {
                float2 p0 = *(const float2*)(base + r * 68);
                float2 p1 = *(const float2*)(base + r * 68 + 2);
                d[r][0] = p0.x; d[r][1] = p0.y; d[r][2] = p1.x; d[r][3] = p1.y;
            }
            float R[4][4];
            #pragma unroll
            for (int r = 0; r < 4; r++) {
                R[r][0] = d[r][0] - d[r][2];
                R[r][1] = d[r][1] + d[r][2];
                R[r][2] = d[r][2] - d[r][1];
                R[r][3] = d[r][1] - d[r][3];
            }
            #pragma unroll
            for (int s = 0; s < 4; s++) {
                V[((0 * 4 + s) * 27 + c) * 64 + t] = R[0][s] - R[2][s];
                V[((1 * 4 + s) * 27 + c) * 64 + t] = R[1][s] + R[2][s];
                V[((2 * 4 + s) * 27 + c) * 64 + t] = R[2][s] - R[1][s];
                V[((3 * 4 + s) * 27 + c) * 64 + t] = R[1][s] - R[3][s];
            }
        }
    }
    __syncthreads();

    // --- 16 position-GEMMs with fused output transform (5 oc per warp) ---
    float2 Y[4][5];
    #pragma unroll
    for (int q = 0; q < 4; q++)
        #pragma unroll
        for (int j = 0; j < 5; j++) Y[q][j] = make_float2(0.f, 0.f);

    #pragma unroll 1
    for (int k = 0; k < 16; k++) {
        if (k + 1 < 16) {
            const char* src = (const char*)g_U + (size_t)(k + 1) * UKB;
            uint32_t dst = sbase + SM_U + ((k + 1) & 1) * UKB;
            for (int j = tid; j < UKB / 16; j += 512)
                CP16(dst + j * 16, src + j * 16);
            CP_COMMIT();
            CP_WAIT1();
        } else {
            CP_WAIT0();
        }
        __syncthreads();

        const float* Uk = (const float*)(smem + SM_U + (k & 1) * UKB) + wid * 8;
        const float2* Vk = (const float2*)(smem + SM_V) + k * 27 * 32 + lane;

        float2 m[5];
        #pragma unroll
        for (int j = 0; j < 5; j++) m[j] = make_float2(0.f, 0.f);
        #pragma unroll 3
        for (int c = 0; c < 27; c++) {
            float2 v = Vk[c * 32];
            float4 ua = *(const float4*)(Uk + c * UCOL);
            float ub = Uk[c * UCOL + 4];
            m[0].x = fmaf(ua.x, v.x, m[0].x); m[0].y = fmaf(ua.x, v.y, m[0].y);
            m[1].x = fmaf(ua.y, v.x, m[1].x); m[1].y = fmaf(ua.y, v.y, m[1].y);
            m[2].x = fmaf(ua.z, v.x, m[2].x); m[2].y = fmaf(ua.z, v.y, m[2].y);
            m[3].x = fmaf(ua.w, v.x, m[3].x); m[3].y = fmaf(ua.w, v.y, m[3].y);
            m[4].x = fmaf(ub,   v.x, m[4].x); m[4].y = fmaf(ub,   v.y, m[4].y);
        }

        // output-transform accumulation: coef(p,q) = A_p[r]*A_q[s]
        int r = k >> 2, s = k & 3;
        float A0r = (r == 3) ? 0.f : 1.f;
        float A1r = (r == 0) ? 0.f : ((r == 1) ? 1.f : -1.f);
        float A0s = (s == 3) ? 0.f : 1.f;
        float A1s = (s == 0) ? 0.f : ((s == 1) ? 1.f : -1.f);
        float cc[4] = { A0r * A0s, A0r * A1s, A1r * A0s, A1r * A1s };
        #pragma unroll
        for (int q = 0; q < 4; q++) {
            if (cc[q] != 0.f) {
                #pragma unroll
                for (int j = 0; j < 5; j++) {
                    Y[q][j].x = fmaf(cc[q], m[j].x, Y[q][j].x);
                    Y[q][j].y = fmaf(cc[q], m[j].y, Y[q][j].y);
                }
            }
        }
        __syncthreads();
    }

    // --- oc80 pass: warp w computes m80 for k=w over still-resident V ---
    {
        float2 m80 = make_float2(0.f, 0.f);
        const float2* Vw = (const float2*)(smem + SM_V) + wid * 27 * 32 + lane;
        const float* U80 = g_U80 + wid * 27;
        #pragma unroll 3
        for (int c = 0; c < 27; c++) {
            float u = __ldg(U80 + c);
            float2 v = Vw[c * 32];
            m80.x = fmaf(u, v.x, m80.x);
            m80.y = fmaf(u, v.y, m80.y);
        }
        float* M = (float*)(smem + SM_M80);
        M[wid * 64 + 2 * lane]     = m80.x;
        M[wid * 64 + 2 * lane + 1] = m80.y;
    }

    // --- main epilogue: bias + STG.128 (ocs 0..79) ---
    {
        const float* bias = (const float*)(smem + SM_BIAS);
        const int xcol = 64 * bx + 4 * (lane & 15);
        const int row0 = 4 * by + 2 * (lane >> 4);
        const size_t base = (size_t)bz * HWSZ + xcol;
        #pragma unroll
        for (int j = 0; j < 5; j++) {
            int oc = 5 * wid + j;
            float bv = bias[oc];
            float* plane = g_conv + (size_t)oc * NPIX + base;
            float4 r0v = make_float4(Y[0][j].x + bv, Y[1][j].x + bv,
                                     Y[0][j].y + bv, Y[1][j].y + bv);
            float4 r1v = make_float4(Y[2][j].x + bv, Y[3][j].x + bv,
                                     Y[2][j].y + bv, Y[3][j].y + bv);
            *(float4*)(plane + (size_t)row0 * WW) = r0v;
            *(float4*)(plane + (size_t)(row0 + 1) * WW) = r1v;
        }
    }

    __syncthreads();   // M complete

    // --- oc80 reduction + store by warp 0 (same tile indexing as main epilogue) ---
    if (wid == 0) {
        const float* M = (const float*)(smem + SM_M80);
        float Y0[4] = {0.f, 0.f, 0.f, 0.f};   // tile 2*lane
        float Y1[4] = {0.f, 0.f, 0.f, 0.f};   // tile 2*lane+1
        #pragma unroll
        for (int k = 0; k < 16; k++) {
            float m0 = M[k * 64 + 2 * lane];
            float m1 = M[k * 64 + 2 * lane + 1];
            int r = k >> 2, s = k & 3;
            float A0r = (r == 3) ? 0.f : 1.f;
            float A1r = (r == 0) ? 0.f : ((r == 1) ? 1.f : -1.f);
            float A0s = (s == 3) ? 0.f : 1.f;
            float A1s = (s == 0) ? 0.f : ((s == 1) ? 1.f : -1.f);
            float c00 = A0r * A0s, c01 = A0r * A1s, c10 = A1r * A0s, c11 = A1r * A1s;
            Y0[0] = fmaf(c00, m0, Y0[0]); Y0[1] = fmaf(c01, m0, Y0[1]);
            Y0[2] = fmaf(c10, m0, Y0[2]); Y0[3] = fmaf(c11, m0, Y0[3]);
            Y1[0] = fmaf(c00, m1, Y1[0]); Y1[1] = fmaf(c01, m1, Y1[1]);
            Y1[2] = fmaf(c10, m1, Y1[2]); Y1[3] = fmaf(c11, m1, Y1[3]);
        }
        const float bv = ((const float*)(smem + SM_BIAS))[80];
        const int xcol = 64 * bx + 4 * (lane & 15);
        const int row0 = 4 * by + 2 * (lane >> 4);
        float* plane = g_conv + (size_t)80 * NPIX + (size_t)bz * HWSZ + xcol;
        float4 r0v = make_float4(Y0[0] + bv, Y0[1] + bv, Y1[0] + bv, Y1[1] + bv);
        float4 r1v = make_float4(Y0[2] + bv, Y0[3] + bv, Y1[2] + bv, Y1[3] + bv);
        *(float4*)(plane + (size_t)row0 * WW) = r0v;
        *(float4*)(plane + (size_t)(row0 + 1) * WW) = r1v;
    }
}

// ---------------- propagation: softmax + bilinear-zeros + confidence blend ----------------
__device__ __constant__ float TAPX[9] = {-1.f, 0.f, 1.f, -1.f, 0.f, 1.f, -1.f, 0.f, 1.f};
__device__ __constant__ float TAPY[9] = {-1.f, -1.f, -1.f, 0.f, 0.f, 0.f, 1.f, 1.f, 1.f};

__global__ void prop_kernel(const float* __restrict__ prev,
                            const float* __restrict__ sp_dep,
                            const float* __restrict__ confid,
                            float* __restrict__ out_cur,
                            float* __restrict__ pred_out,
                            const float* __restrict__ feat_src,
                            float* __restrict__ feat_dst,
                            int iter) {
    int p = blockIdx.x * blockDim.x + threadIdx.x;
    if (p >= NPIX) return;
    int b = p / HWSZ;
    int rem = p % HWSZ;
    int y = rem / WW;
    int x = rem % WW;
    const float* img = prev + (size_t)b * HWSZ;

    // ---- front-load all independent global reads (max MLP) ----
    float araw[9], ox[9], oy[9];
    #pragma unroll
    for (int t = 0; t < 9; t++)
        araw[t] = __ldg(&g_conv[(size_t)(54 + iter * 9 + t) * NPIX + p]);
    #pragma unroll
    for (int t = 0; t < 9; t++) {
        ox[t] = __ldg(&g_conv[(size_t)((iter * 9 + t) * 2) * NPIX + p]);
        oy[t] = __ldg(&g_conv[(size_t)((iter * 9 + t) * 2 + 1) * NPIX + p]);
    }
    float sp = __ldg(&sp_dep[p]);
    float cfr = __ldg(&confid[p]);

    // softmax weights
    float mx = araw[0];
    #pragma unroll
    for (int t = 1; t < 9; t++) mx = fmaxf(mx, araw[t]);
    float wv[9];
    float s = 0.f;
    #pragma unroll
    for (int t = 0; t < 9; t++) { wv[t] = __expf(araw[t] - mx); s += wv[t]; }
    float inv = 1.f / s;

    float agg = 0.f;
    #pragma unroll
    for (int t = 0; t < 9; t++) {
        float px = ox[t] + TAPX[t] + (float)x;
        float py = oy[t] + TAPY[t] + (float)y;
        float x0f = floorf(px), y0f = floorf(py);
        int xi = (int)x0f, yi = (int)y0f;
        float wx = px - x0f, wy = py - y0f;

        float v00 = 0.f, v01 = 0.f, v10 = 0.f, v11 = 0.f;
        bool xa = (xi >= 0) & (xi < WW);
        bool xb2 = (xi + 1 >= 0) & (xi + 1 < WW);
        bool ya = (yi >= 0) & (yi < HH);
        bool yb = (yi + 1 >= 0) & (yi + 1 < HH);
        if (ya) {
            const float* r0 = img + (size_t)yi * WW;
            if (xa) v00 = __ldg(r0 + xi);
            if (xb2) v01 = __ldg(r0 + xi + 1);
        }
        if (yb) {
            const float* r1 = img + (size_t)(yi + 1) * WW;
            if (xa) v10 = __ldg(r1 + xi);
            if (xb2) v11 = __ldg(r1 + xi + 1);
        }
        float v = (1.f - wy) * ((1.f - wx) * v00 + wx * v01)
                + wy * ((1.f - wx) * v10 + wx * v11);
        agg += wv[t] * v;
    }
    agg *= inv;

    float cf = 1.f / (1.f + __expf(-cfr));
    float sg = (sp > 0.f) ? 1.f : ((sp < 0.f) ? -1.f : 0.f);
    cf *= sg;
    float o = (1.f - cf) * agg + cf * sp;

    out_cur[p] = o;
    if (pred_out) pred_out[p] = o;
    if (feat_dst) feat_dst[p] = feat_src[p];
}

// ---------------- launch ----------------
extern "C" void kernel_launch(void* const* d_in, const int* in_sizes, int n_in,
                              void* d_out, int out_size) {
    const float* input  = (const float*)d_in[0];
    const float* guide  = (const float*)d_in[1];
    const float* sp_dep = (const float*)d_in[2];
    const float* confid = (const float*)d_in[3];
    const float* conv_w = (const float*)d_in[4];
    const float* conv_b = (const float*)d_in[5];

    float* out = (float*)d_out;
    float* pred = out;
    float* feat = out + NPIX;
    float* inter = out + 2 * (size_t)NPIX;

    static bool attr_set = false;
    if (!attr_set) {
        cudaFuncSetAttribute(wino_kernel, cudaFuncAttributeMaxDynamicSharedMemorySize, SM_TOTAL);
        attr_set = true;
    }

    prep_kernel<<<(27 * UCOL + 27 + 255) / 256, 256>>>(conv_w);

    dim3 wgrid(GX, GY, BB);
    wino_kernel<<<wgrid, 512, SM_TOTAL>>>(guide, conv_b);

    int pb = (NPIX + 255) / 256;
    prop_kernel<<<pb, 256>>>(input, sp_dep, confid, inter, nullptr, input, feat, 0);
    prop_kernel<<<pb, 256>>>(inter, sp_dep, confid, inter + NPIX, nullptr, nullptr, nullptr, 1);
    prop_kernel<<<pb, 256>>>(inter + NPIX, sp_dep, confid, inter + 2 * (size_t)NPIX, pred, nullptr, nullptr, 2);
}